// round 15
// baseline (speedup 1.0000x reference)
#include <cuda_runtime.h>
#include <cuda_fp16.h>
#include <math.h>
#include <stdint.h>

#define T_TOK   2048
#define HDIM    1024
#define NEXP    16
#define IDIM    512
#define TOPK    4
#define NASSIGN (T_TOK * TOPK)
#define ROWPAD  128

// ---------------- scratch ----------------
__device__ int    g_cnt[NEXP];
__device__ int    g_off[NEXP];
__device__ int    g_done;
__device__ int    g_tokens[NEXP * T_TOK];
__device__ float  g_wexp[NEXP * T_TOK];                   // combine weight per (expert, slot)
__device__ __half g_xh[T_TOK * HDIM];
__device__ __half g_hidden[(NASSIGN + ROWPAD) * IDIM];

// ---------------- helpers ----------------
__device__ __forceinline__ uint32_t smem_u32(const void* p) {
    uint32_t a;
    asm("{ .reg .u64 t; cvta.to.shared.u64 t, %1; cvt.u32.u64 %0, t; }" : "=r"(a) : "l"(p));
    return a;
}
__device__ __forceinline__ unsigned h2u(__half2 h) { return *(unsigned*)&h; }
__device__ __forceinline__ void cp16(uint32_t dst, const void* src) {
    asm volatile("cp.async.ca.shared.global [%0], [%1], 16;" :: "r"(dst), "l"(src) : "memory");
}
#define CP_COMMIT() asm volatile("cp.async.commit_group;" ::: "memory")
#define CP_WAIT0()  asm volatile("cp.async.wait_group 0;" ::: "memory")

__device__ __forceinline__ void red_add(float* p, float v) {
    asm volatile("red.global.add.f32 [%0], %1;" :: "l"(p), "f"(v) : "memory");
}
__device__ __forceinline__ void ldsm_x4(unsigned& r0, unsigned& r1, unsigned& r2,
                                        unsigned& r3, uint32_t a) {
    asm volatile("ldmatrix.sync.aligned.m8n8.x4.shared.b16 {%0,%1,%2,%3}, [%4];"
                 : "=r"(r0), "=r"(r1), "=r"(r2), "=r"(r3) : "r"(a));
}
__device__ __forceinline__ void ldsm_x4t(unsigned& r0, unsigned& r1, unsigned& r2,
                                         unsigned& r3, uint32_t a) {
    asm volatile("ldmatrix.sync.aligned.m8n8.x4.trans.shared.b16 {%0,%1,%2,%3}, [%4];"
                 : "=r"(r0), "=r"(r1), "=r"(r2), "=r"(r3) : "r"(a));
}
__device__ __forceinline__ void mma_f16(float d[4], const unsigned a[4],
                                        unsigned b0, unsigned b1) {
    asm volatile(
        "mma.sync.aligned.m16n8k16.row.col.f32.f16.f16.f32 "
        "{%0,%1,%2,%3}, {%4,%5,%6,%7}, {%8,%9}, {%0,%1,%2,%3};"
        : "+f"(d[0]), "+f"(d[1]), "+f"(d[2]), "+f"(d[3])
        : "r"(a[0]), "r"(a[1]), "r"(a[2]), "r"(a[3]), "r"(b0), "r"(b1));
}

// A smem: m-major, 128 rows x 40 halves (32 used), 20 words/row
#define A_RW   20
#define ASTW   (128 * A_RW)
#define ASTB   (ASTW * 4)
// B smem (gemm1): k-major, 32 rows x 72 halves (64 used), 36 words/row
#define B_RW   36
#define BSTW   (32 * B_RW)
#define BSTB   (BSTW * 4)
// B smem (gemm2): k-major, 32 rows x 136 halves (128 used), 68 words/row
#define B2_RW  68
#define B2STW  (32 * B2_RW)
#define B2STB  (B2STW * 4)

// ---------------- router: R8 math + fused scan + output zeroing ----------------
__global__ void router_kernel(const float* __restrict__ x,
                              const float* __restrict__ wgt,
                              float* __restrict__ out,
                              float* __restrict__ logits_out,
                              int write_logits) {
    // zero this block's 16 output rows (required before gemm2's red.add)
    {
        float4 z = make_float4(0.f, 0.f, 0.f, 0.f);
        float4* orow = (float4*)(out + (size_t)blockIdx.x * 16 * HDIM);
        #pragma unroll
        for (int i = 0; i < 16; i++)
            orow[i * 256 + threadIdx.x] = z;
    }

    __shared__ float sl[16][17];
    int tl = threadIdx.x >> 4;
    int e  = threadIdx.x & 15;
    int t  = blockIdx.x * 16 + tl;

    const float* xr = x + (size_t)t * HDIM;
    float acc = 0.f;
    #pragma unroll 4
    for (int h = 0; h < HDIM; h += 4) {
        float4 xv = *(const float4*)(xr + h);
        acc += xv.x * wgt[(h + 0) * NEXP + e];
        acc += xv.y * wgt[(h + 1) * NEXP + e];
        acc += xv.z * wgt[(h + 2) * NEXP + e];
        acc += xv.w * wgt[(h + 3) * NEXP + e];
    }
    sl[tl][e] = acc;
    if (write_logits) logits_out[(size_t)t * NEXP + e] = acc;

    {
        const float* xs = xr + e * 64;
        __half2* xt = (__half2*)(g_xh + (size_t)t * HDIM + e * 64);
        #pragma unroll
        for (int h = 0; h < 64; h += 4) {
            float4 v = *(const float4*)(xs + h);
            xt[h / 2]     = __floats2half2_rn(v.x, v.y);
            xt[h / 2 + 1] = __floats2half2_rn(v.z, v.w);
        }
    }
    __syncthreads();

    if (e == 0) {
        float v[NEXP];
        #pragma unroll
        for (int i = 0; i < NEXP; i++) v[i] = sl[tl][i];
        int   sel[TOPK]; float selv[TOPK];
        #pragma unroll
        for (int k = 0; k < TOPK; k++) {
            int bi = 0; float bv = -INFINITY;
            #pragma unroll
            for (int i = 0; i < NEXP; i++)
                if (v[i] > bv) { bv = v[i]; bi = i; }
            sel[k] = bi; selv[k] = bv; v[bi] = -INFINITY;
        }
        float mx = selv[0];
        float ex[TOPK], s = 0.f;
        #pragma unroll
        for (int k = 0; k < TOPK; k++) { ex[k] = expf(selv[k] - mx); s += ex[k]; }
        float inv = 1.f / s;
        #pragma unroll
        for (int k = 0; k < TOPK; k++) {
            int ee   = sel[k];
            int slot = atomicAdd(&g_cnt[ee], 1);
            g_tokens[ee * T_TOK + slot] = t;
            g_wexp[ee * T_TOK + slot]   = ex[k] * inv;
        }
    }
    __syncthreads();

    if (threadIdx.x == 0) {
        __threadfence();
        int d = atomicAdd(&g_done, 1);
        if (d == gridDim.x - 1) {
            g_done = 0;
            int o = 0;
            #pragma unroll
            for (int ee = 0; ee < NEXP; ee++) {
                int c = atomicAdd(&g_cnt[ee], 0);
                g_off[ee] = o;
                o += c;
                g_cnt[ee] = c;     // keep value (read is destructive-free; just rewrite)
            }
        }
    }
}

// ======== gemm1: fp16 mma.sync + ldmatrix(x4t), 128x64 block, BK=32, SiLU*up ========
// grid (IDIM/64=8, 16, NEXP), 256 threads  — identical to R14
__global__ __launch_bounds__(256, 2) void moe_gemm1(
        const float* __restrict__ wg_all,
        const float* __restrict__ wu_all) {
    int e   = blockIdx.z;
    int cnt = g_cnt[e];
    int m0  = blockIdx.y * 128;
    if (m0 >= cnt) return;
    int n0  = blockIdx.x * 64;

    const float* wg = wg_all + (size_t)e * HDIM * IDIM;
    const float* wu = wu_all + (size_t)e * HDIM * IDIM;

    __shared__ __align__(16) unsigned Ash[2 * ASTW];
    __shared__ __align__(16) unsigned Bgh[2 * BSTW];
    __shared__ __align__(16) unsigned Buh[2 * BSTW];
    __shared__ int stok[128];

    int tid = threadIdx.x;
    if (tid < 128) {
        int m = m0 + tid;
        stok[tid] = (m < cnt) ? g_tokens[e * T_TOK + m] : g_tokens[e * T_TOK];
    }
    __syncthreads();

    int lane = tid & 31, warp = tid >> 5;
    int wm = (warp >> 1) * 32, wn = (warp & 1) * 32;
    int gid = lane >> 2, p = lane & 3;

    uint32_t As_u = smem_u32(Ash);
    uint32_t Bg_u = smem_u32(Bgh);
    uint32_t Bu_u = smem_u32(Buh);

    uint32_t a_lds  = As_u + (((wm + (lane & 15)) * A_RW + (lane >> 4) * 4) << 2);
    uint32_t bg_lds = Bg_u + ((((lane & 15) * B_RW) + (wn >> 1) + ((lane >> 4) << 2)) << 2);
    uint32_t bu_lds = Bu_u + ((((lane & 15) * B_RW) + (wn >> 1) + ((lane >> 4) << 2)) << 2);

    int arow = tid >> 1, achunk = tid & 1;
    const __half* aptr = g_xh + (size_t)stok[arow] * HDIM + achunk * 16;
    uint32_t asts = As_u + arow * (A_RW * 4) + achunk * 32;

    int bkr = tid >> 3, bnq = tid & 7;
    const float* gptr = wg + (size_t)bkr * IDIM + n0 + bnq * 8;
    const float* uptr = wu + (size_t)bkr * IDIM + n0 + bnq * 8;
    int bsts = bkr * B_RW + bnq * 4;

    float accg[2][4][4] = {}, accu[2][4][4] = {};

    {
        cp16(asts, aptr);
        cp16(asts + 16, aptr + 8);
        float4 g0 = *(const float4*)gptr;
        float4 g1 = *(const float4*)(gptr + 4);
        float4 u0 = *(const float4*)uptr;
        float4 u1 = *(const float4*)(uptr + 4);
        *(uint4*)&Bgh[bsts] = make_uint4(
            h2u(__floats2half2_rn(g0.x, g0.y)), h2u(__floats2half2_rn(g0.z, g0.w)),
            h2u(__floats2half2_rn(g1.x, g1.y)), h2u(__floats2half2_rn(g1.z, g1.w)));
        *(uint4*)&Buh[bsts] = make_uint4(
            h2u(__floats2half2_rn(u0.x, u0.y)), h2u(__floats2half2_rn(u0.z, u0.w)),
            h2u(__floats2half2_rn(u1.x, u1.y)), h2u(__floats2half2_rn(u1.z, u1.w)));
        CP_COMMIT();
        CP_WAIT0();
    }
    __syncthreads();

    #pragma unroll 1
    for (int it = 0; it < HDIM / 32; it++) {
        int s = it & 1;
        bool more = (it + 1) < HDIM / 32;

        float4 g0, g1, u0, u1;
        if (more) {
            int k0 = (it + 1) * 32;
            cp16(asts + (s ^ 1) * ASTB, aptr + k0);
            cp16(asts + (s ^ 1) * ASTB + 16, aptr + k0 + 8);
            CP_COMMIT();
            g0 = *(const float4*)(gptr + (size_t)k0 * IDIM);
            g1 = *(const float4*)(gptr + (size_t)k0 * IDIM + 4);
            u0 = *(const float4*)(uptr + (size_t)k0 * IDIM);
            u1 = *(const float4*)(uptr + (size_t)k0 * IDIM + 4);
        }

        #pragma unroll
        for (int kc = 0; kc < 2; kc++) {
            unsigned af[2][4];
            #pragma unroll
            for (int mf = 0; mf < 2; mf++)
                ldsm_x4(af[mf][0], af[mf][1], af[mf][2], af[mf][3],
                        a_lds + s * ASTB + kc * 32 + mf * (16 * A_RW * 4));
            #pragma unroll
            for (int nf2 = 0; nf2 < 2; nf2++) {
                unsigned bg[4], bu[4];
                uint32_t bo = s * BSTB + kc * (16 * B_RW * 4) + nf2 * 32;
                ldsm_x4t(bg[0], bg[1], bg[2], bg[3], bg_lds + bo);
                ldsm_x4t(bu[0], bu[1], bu[2], bu[3], bu_lds + bo);
                int nf = nf2 * 2;
                mma_f16(accg[0][nf],     af[0], bg[0], bg[1]);
                mma_f16(accg[1][nf],     af[1], bg[0], bg[1]);
                mma_f16(accg[0][nf + 1], af[0], bg[2], bg[3]);
                mma_f16(accg[1][nf + 1], af[1], bg[2], bg[3]);
                mma_f16(accu[0][nf],     af[0], bu[0], bu[1]);
                mma_f16(accu[1][nf],     af[1], bu[0], bu[1]);
                mma_f16(accu[0][nf + 1], af[0], bu[2], bu[3]);
                mma_f16(accu[1][nf + 1], af[1], bu[2], bu[3]);
            }
        }

        if (more) {
            int nb = (s ^ 1) * BSTW;
            *(uint4*)&Bgh[nb + bsts] = make_uint4(
                h2u(__floats2half2_rn(g0.x, g0.y)), h2u(__floats2half2_rn(g0.z, g0.w)),
                h2u(__floats2half2_rn(g1.x, g1.y)), h2u(__floats2half2_rn(g1.z, g1.w)));
            *(uint4*)&Buh[nb + bsts] = make_uint4(
                h2u(__floats2half2_rn(u0.x, u0.y)), h2u(__floats2half2_rn(u0.z, u0.w)),
                h2u(__floats2half2_rn(u1.x, u1.y)), h2u(__floats2half2_rn(u1.z, u1.w)));
            CP_WAIT0();
        }
        __syncthreads();
    }

    int base = g_off[e] + m0;
    #pragma unroll
    for (int mf = 0; mf < 2; mf++) {
        int r0 = wm + mf * 16 + gid;
        int r1 = r0 + 8;
        #pragma unroll
        for (int nf = 0; nf < 4; nf++) {
            int col = n0 + wn + nf * 8 + 2 * p;
            if (m0 + r0 < cnt) {
                float g0 = accg[mf][nf][0], g1 = accg[mf][nf][1];
                float u0 = accu[mf][nf][0], u1 = accu[mf][nf][1];
                *(__half2*)(g_hidden + (size_t)(base + r0) * IDIM + col)
                    = __floats2half2_rn((g0 / (1.f + __expf(-g0))) * u0,
                                        (g1 / (1.f + __expf(-g1))) * u1);
            }
            if (m0 + r1 < cnt) {
                float g2 = accg[mf][nf][2], g3 = accg[mf][nf][3];
                float u2 = accu[mf][nf][2], u3 = accu[mf][nf][3];
                *(__half2*)(g_hidden + (size_t)(base + r1) * IDIM + col)
                    = __floats2half2_rn((g2 / (1.f + __expf(-g2))) * u2,
                                        (g3 / (1.f + __expf(-g3))) * u3);
            }
        }
    }
}

// ======== gemm2: fp16 mma + ldmatrix(x4t), 128x128 block, fused weighted scatter ========
// grid (HDIM/128=8, 16, NEXP), 256 threads, 8 warps = 4m x 2n
__global__ __launch_bounds__(256, 2) void moe_gemm2(const float* __restrict__ wd_all,
                                                    float* __restrict__ out) {
    int e   = blockIdx.z;
    int cnt = g_cnt[e];
    int m0  = blockIdx.y * 128;
    if (m0 >= cnt) return;
    int n0  = blockIdx.x * 128;

    const float* wd = wd_all + (size_t)e * IDIM * HDIM;
    int base = g_off[e] + m0;

    __shared__ __align__(16) unsigned Ash[2 * ASTW];
    __shared__ __align__(16) unsigned Bsh[2 * B2STW];

    int tid = threadIdx.x;
    int lane = tid & 31, warp = tid >> 5;
    int wm = (warp >> 1) * 32, wn = (warp & 1) * 64;
    int gid = lane >> 2, p = lane & 3;

    uint32_t As_u = smem_u32(Ash);
    uint32_t Bs_u = smem_u32(Bsh);

    uint32_t a_lds = As_u + (((wm + (lane & 15)) * A_RW + (lane >> 4) * 4) << 2);
    uint32_t b_lds = Bs_u + ((((lane & 15) * B2_RW) + (wn >> 1) + ((lane >> 4) << 2)) << 2);

    int arow = tid >> 1, achunk = tid & 1;
    const __half* aptr = g_hidden + (size_t)(base + arow) * IDIM + achunk * 16;
    uint32_t asts = As_u + arow * (A_RW * 4) + achunk * 32;

    int bkr = tid >> 3, bnq = tid & 7;
    const float* bptr = wd + (size_t)bkr * HDIM + n0 + bnq * 16;
    int bsts = bkr * B2_RW + bnq * 8;

    float acc[2][8][4] = {};

    {
        cp16(asts, aptr);
        cp16(asts + 16, aptr + 8);
        float4 b0 = *(const float4*)bptr;
        float4 b1 = *(const float4*)(bptr + 4);
        float4 b2 = *(const float4*)(bptr + 8);
        float4 b3 = *(const float4*)(bptr + 12);
        *(uint4*)&Bsh[bsts] = make_uint4(
            h2u(__floats2half2_rn(b0.x, b0.y)), h2u(__floats2half2_rn(b0.z, b0.w)),
            h2u(__floats2half2_rn(b1.x, b1.y)), h2u(__floats2half2_rn(b1.z, b1.w)));
        *(uint4*)&Bsh[bsts + 4] = make_uint4(
            h2u(__floats2half2_rn(b2.x, b2.y)), h2u(__floats2half2_rn(b2.z, b2.w)),
            h2u(__floats2half2_rn(b3.x, b3.y)), h2u(__floats2half2_rn(b3.z, b3.w)));
        CP_COMMIT();
        CP_WAIT0();
    }
    __syncthreads();

    #pragma unroll 1
    for (int it = 0; it < IDIM / 32; it++) {
        int s = it & 1;
        bool more = (it + 1) < IDIM / 32;

        float4 b0v, b1v, b2v, b3v;
        if (more) {
            int k0 = (it + 1) * 32;
            cp16(asts + (s ^ 1) * ASTB, aptr + k0);
            cp16(asts + (s ^ 1) * ASTB + 16, aptr + k0 + 8);
            CP_COMMIT();
            b0v = *(const float4*)(bptr + (size_t)k0 * HDIM);
            b1v = *(const float4*)(bptr + (size_t)k0 * HDIM + 4);
            b2v = *(const float4*)(bptr + (size_t)k0 * HDIM + 8);
            b3v = *(const float4*)(bptr + (size_t)k0 * HDIM + 12);
        }

        #pragma unroll
        for (int kc = 0; kc < 2; kc++) {
            unsigned af[2][4];
            #pragma unroll
            for (int mf = 0; mf < 2; mf++)
                ldsm_x4(af[mf][0], af[mf][1], af[mf][2], af[mf][3],
                        a_lds + s * ASTB + kc * 32 + mf * (16 * A_RW * 4));
            #pragma unroll
            for (int nf2 = 0; nf2 < 4; nf2++) {
                unsigned bb[4];
                uint32_t bo = s * B2STB + kc * (16 * B2_RW * 4) + nf2 * 32;
                ldsm_x4t(bb[0], bb[1], bb[2], bb[3], b_lds + bo);
                int nf = nf2 * 2;
                mma_f16(acc[0][nf],     af[0], bb[0], bb[1]);
                mma_f16(acc[1][nf],     af[1], bb[0], bb[1]);
                mma_f16(acc[0][nf + 1], af[0], bb[2], bb[3]);
                mma_f16(acc[1][nf + 1], af[1], bb[2], bb[3]);
            }
        }

        if (more) {
            int nb = (s ^ 1) * B2STW;
            *(uint4*)&Bsh[nb + bsts] = make_uint4(
                h2u(__floats2half2_rn(b0v.x, b0v.y)), h2u(__floats2half2_rn(b0v.z, b0v.w)),
                h2u(__floats2half2_rn(b1v.x, b1v.y)), h2u(__floats2half2_rn(b1v.z, b1v.w)));
            *(uint4*)&Bsh[nb + bsts + 4] = make_uint4(
                h2u(__floats2half2_rn(b2v.x, b2v.y)), h2u(__floats2half2_rn(b2v.z, b2v.w)),
                h2u(__floats2half2_rn(b3v.x, b3v.y)), h2u(__floats2half2_rn(b3v.z, b3v.w)));
            CP_WAIT0();
        }
        __syncthreads();
    }

    // fused epilogue: out[token] += w * acc   (red.global.add)
    #pragma unroll
    for (int mf = 0; mf < 2; mf++) {
        int r0 = wm + mf * 16 + gid;
        int r1 = r0 + 8;
        int  v0 = (m0 + r0 < cnt), v1 = (m0 + r1 < cnt);
        int  t0 = 0, t1 = 0;
        float w0 = 0.f, w1 = 0.f;
        if (v0) { t0 = g_tokens[e * T_TOK + m0 + r0]; w0 = g_wexp[e * T_TOK + m0 + r0]; }
        if (v1) { t1 = g_tokens[e * T_TOK + m0 + r1]; w1 = g_wexp[e * T_TOK + m0 + r1]; }
        float* o0 = out + (size_t)t0 * HDIM;
        float* o1 = out + (size_t)t1 * HDIM;
        #pragma unroll
        for (int nf = 0; nf < 8; nf++) {
            int col = n0 + wn + nf * 8 + 2 * p;
            if (v0) {
                red_add(o0 + col,     w0 * acc[mf][nf][0]);
                red_add(o0 + col + 1, w0 * acc[mf][nf][1]);
            }
            if (v1) {
                red_add(o1 + col,     w1 * acc[mf][nf][2]);
                red_add(o1 + col + 1, w1 * acc[mf][nf][3]);
            }
        }
    }
    // reset counters for next replay (one block does it; gemm2 is the last writer of g_cnt readers)
    if (blockIdx.x == 0 && blockIdx.y == 0 && blockIdx.z == 0 && tid < NEXP)
        ;  // g_cnt reset moved to a dedicated tail below via last-block ticket in router
}

// tiny tail kernel: reset g_cnt for the next replay (replaces combine's reset)
__global__ void reset_kernel() { if (threadIdx.x < NEXP) g_cnt[threadIdx.x] = 0; }

// ---------------- launch ----------------
extern "C" void kernel_launch(void* const* d_in, const int* in_sizes, int n_in,
                              void* d_out, int out_size) {
    const float* x   = (const float*)d_in[0];
    const float* wgt = (const float*)d_in[1];
    const float* wgp = (const float*)d_in[2];
    const float* wup = (const float*)d_in[3];
    const float* wdp = (const float*)d_in[4];
    float* out = (float*)d_out;

    int write_logits = (out_size >= T_TOK * HDIM + T_TOK * NEXP) ? 1 : 0;
    float* logits_out = out + (size_t)T_TOK * HDIM;

    router_kernel<<<T_TOK / 16, 256>>>(x, wgt, out, logits_out, write_logits);
    moe_gemm1<<<dim3(IDIM / 64, T_TOK / 128, NEXP), 256>>>(wgp, wup);
    moe_gemm2<<<dim3(HDIM / 128, T_TOK / 128, NEXP), 256>>>(wdp, out);
    reset_kernel<<<1, 32>>>();
}

// round 16
// speedup vs baseline: 1.0209x; 1.0209x over previous
#include <cuda_runtime.h>
#include <cuda_fp16.h>
#include <math.h>
#include <stdint.h>

#define T_TOK   2048
#define HDIM    1024
#define NEXP    16
#define IDIM    512
#define TOPK    4
#define NASSIGN (T_TOK * TOPK)
#define ROWPAD  128

// ---------------- scratch ----------------
__device__ int    g_cnt[NEXP];
__device__ int    g_off[NEXP];
__device__ int    g_done;
__device__ int    g_tokens[NEXP * T_TOK];
__device__ int    g_sel_e[NASSIGN];
__device__ int    g_sel_slot[NASSIGN];
__device__ float  g_sel_w[NASSIGN];
__device__ __half g_xh[T_TOK * HDIM];
__device__ __half g_hidden[(NASSIGN + ROWPAD) * IDIM];
__device__ __half g_downh[(NASSIGN + ROWPAD) * HDIM];     // fp16 down output

// ---------------- helpers ----------------
__device__ __forceinline__ uint32_t smem_u32(const void* p) {
    uint32_t a;
    asm("{ .reg .u64 t; cvta.to.shared.u64 t, %1; cvt.u32.u64 %0, t; }" : "=r"(a) : "l"(p));
    return a;
}
__device__ __forceinline__ unsigned h2u(__half2 h) { return *(unsigned*)&h; }
__device__ __forceinline__ void cp16(uint32_t dst, const void* src) {
    asm volatile("cp.async.ca.shared.global [%0], [%1], 16;" :: "r"(dst), "l"(src) : "memory");
}
#define CP_COMMIT() asm volatile("cp.async.commit_group;" ::: "memory")
#define CP_WAIT0()  asm volatile("cp.async.wait_group 0;" ::: "memory")

__device__ __forceinline__ void ldsm_x4(unsigned& r0, unsigned& r1, unsigned& r2,
                                        unsigned& r3, uint32_t a) {
    asm volatile("ldmatrix.sync.aligned.m8n8.x4.shared.b16 {%0,%1,%2,%3}, [%4];"
                 : "=r"(r0), "=r"(r1), "=r"(r2), "=r"(r3) : "r"(a));
}
__device__ __forceinline__ void ldsm_x4t(unsigned& r0, unsigned& r1, unsigned& r2,
                                         unsigned& r3, uint32_t a) {
    asm volatile("ldmatrix.sync.aligned.m8n8.x4.trans.shared.b16 {%0,%1,%2,%3}, [%4];"
                 : "=r"(r0), "=r"(r1), "=r"(r2), "=r"(r3) : "r"(a));
}
__device__ __forceinline__ void mma_f16(float d[4], const unsigned a[4],
                                        unsigned b0, unsigned b1) {
    asm volatile(
        "mma.sync.aligned.m16n8k16.row.col.f32.f16.f16.f32 "
        "{%0,%1,%2,%3}, {%4,%5,%6,%7}, {%8,%9}, {%0,%1,%2,%3};"
        : "+f"(d[0]), "+f"(d[1]), "+f"(d[2]), "+f"(d[3])
        : "r"(a[0]), "r"(a[1]), "r"(a[2]), "r"(a[3]), "r"(b0), "r"(b1));
}

// A smem: m-major, 128 rows x 40 halves (32 used), 20 words/row
#define A_RW   20
#define ASTW   (128 * A_RW)
#define ASTB   (ASTW * 4)
// B smem (gemm1): k-major, 32 rows x 72 halves (64 used), 36 words/row
#define B_RW   36
#define BSTW   (32 * B_RW)
#define BSTB   (BSTW * 4)
// B smem (gemm2): k-major, 32 rows x 136 halves (128 used), 68 words/row
#define B2_RW  68
#define B2STW  (32 * B2_RW)
#define B2STB  (B2STW * 4)

// ---------------- router (R8 math) + fused scan via last-block ticket ----------------
__global__ void router_kernel(const float* __restrict__ x,
                              const float* __restrict__ wgt,
                              float* __restrict__ logits_out,
                              int write_logits) {
    __shared__ float sl[16][17];
    int tl = threadIdx.x >> 4;
    int e  = threadIdx.x & 15;
    int t  = blockIdx.x * 16 + tl;

    const float* xr = x + (size_t)t * HDIM;
    float acc = 0.f;
    #pragma unroll 4
    for (int h = 0; h < HDIM; h += 4) {
        float4 xv = *(const float4*)(xr + h);
        acc += xv.x * wgt[(h + 0) * NEXP + e];
        acc += xv.y * wgt[(h + 1) * NEXP + e];
        acc += xv.z * wgt[(h + 2) * NEXP + e];
        acc += xv.w * wgt[(h + 3) * NEXP + e];
    }
    sl[tl][e] = acc;
    if (write_logits) logits_out[(size_t)t * NEXP + e] = acc;

    {
        const float* xs = xr + e * 64;
        __half2* xt = (__half2*)(g_xh + (size_t)t * HDIM + e * 64);
        #pragma unroll
        for (int h = 0; h < 64; h += 4) {
            float4 v = *(const float4*)(xs + h);
            xt[h / 2]     = __floats2half2_rn(v.x, v.y);
            xt[h / 2 + 1] = __floats2half2_rn(v.z, v.w);
        }
    }
    __syncthreads();

    if (e == 0) {
        float v[NEXP];
        #pragma unroll
        for (int i = 0; i < NEXP; i++) v[i] = sl[tl][i];
        int   sel[TOPK]; float selv[TOPK];
        #pragma unroll
        for (int k = 0; k < TOPK; k++) {
            int bi = 0; float bv = -INFINITY;
            #pragma unroll
            for (int i = 0; i < NEXP; i++)
                if (v[i] > bv) { bv = v[i]; bi = i; }
            sel[k] = bi; selv[k] = bv; v[bi] = -INFINITY;
        }
        float mx = selv[0];
        float ex[TOPK], s = 0.f;
        #pragma unroll
        for (int k = 0; k < TOPK; k++) { ex[k] = expf(selv[k] - mx); s += ex[k]; }
        float inv = 1.f / s;
        #pragma unroll
        for (int k = 0; k < TOPK; k++) {
            int ee   = sel[k];
            int slot = atomicAdd(&g_cnt[ee], 1);
            g_tokens[ee * T_TOK + slot] = t;
            g_sel_e[t * TOPK + k]    = ee;
            g_sel_slot[t * TOPK + k] = slot;
            g_sel_w[t * TOPK + k]    = ex[k] * inv;
        }
    }
    __syncthreads();

    if (threadIdx.x == 0) {
        __threadfence();
        int d = atomicAdd(&g_done, 1);
        if (d == gridDim.x - 1) {
            g_done = 0;
            int o = 0;
            #pragma unroll
            for (int ee = 0; ee < NEXP; ee++) {
                int c = atomicAdd(&g_cnt[ee], 0);
                g_off[ee] = o;
                o += c;
            }
        }
    }
}

// ======== gemm1: fp16 mma.sync + ldmatrix(x4t), 128x64 block, BK=32, SiLU*up ========
// grid (IDIM/64=8, 16, NEXP), 256 threads  — identical to R14
__global__ __launch_bounds__(256, 2) void moe_gemm1(
        const float* __restrict__ wg_all,
        const float* __restrict__ wu_all) {
    int e   = blockIdx.z;
    int cnt = g_cnt[e];
    int m0  = blockIdx.y * 128;
    if (m0 >= cnt) return;
    int n0  = blockIdx.x * 64;

    const float* wg = wg_all + (size_t)e * HDIM * IDIM;
    const float* wu = wu_all + (size_t)e * HDIM * IDIM;

    __shared__ __align__(16) unsigned Ash[2 * ASTW];
    __shared__ __align__(16) unsigned Bgh[2 * BSTW];
    __shared__ __align__(16) unsigned Buh[2 * BSTW];
    __shared__ int stok[128];

    int tid = threadIdx.x;
    if (tid < 128) {
        int m = m0 + tid;
        stok[tid] = (m < cnt) ? g_tokens[e * T_TOK + m] : g_tokens[e * T_TOK];
    }
    __syncthreads();

    int lane = tid & 31, warp = tid >> 5;
    int wm = (warp >> 1) * 32, wn = (warp & 1) * 32;
    int gid = lane >> 2, p = lane & 3;

    uint32_t As_u = smem_u32(Ash);
    uint32_t Bg_u = smem_u32(Bgh);
    uint32_t Bu_u = smem_u32(Buh);

    uint32_t a_lds  = As_u + (((wm + (lane & 15)) * A_RW + (lane >> 4) * 4) << 2);
    uint32_t bg_lds = Bg_u + ((((lane & 15) * B_RW) + (wn >> 1) + ((lane >> 4) << 2)) << 2);
    uint32_t bu_lds = Bu_u + ((((lane & 15) * B_RW) + (wn >> 1) + ((lane >> 4) << 2)) << 2);

    int arow = tid >> 1, achunk = tid & 1;
    const __half* aptr = g_xh + (size_t)stok[arow] * HDIM + achunk * 16;
    uint32_t asts = As_u + arow * (A_RW * 4) + achunk * 32;

    int bkr = tid >> 3, bnq = tid & 7;
    const float* gptr = wg + (size_t)bkr * IDIM + n0 + bnq * 8;
    const float* uptr = wu + (size_t)bkr * IDIM + n0 + bnq * 8;
    int bsts = bkr * B_RW + bnq * 4;

    float accg[2][4][4] = {}, accu[2][4][4] = {};

    {
        cp16(asts, aptr);
        cp16(asts + 16, aptr + 8);
        float4 g0 = *(const float4*)gptr;
        float4 g1 = *(const float4*)(gptr + 4);
        float4 u0 = *(const float4*)uptr;
        float4 u1 = *(const float4*)(uptr + 4);
        *(uint4*)&Bgh[bsts] = make_uint4(
            h2u(__floats2half2_rn(g0.x, g0.y)), h2u(__floats2half2_rn(g0.z, g0.w)),
            h2u(__floats2half2_rn(g1.x, g1.y)), h2u(__floats2half2_rn(g1.z, g1.w)));
        *(uint4*)&Buh[bsts] = make_uint4(
            h2u(__floats2half2_rn(u0.x, u0.y)), h2u(__floats2half2_rn(u0.z, u0.w)),
            h2u(__floats2half2_rn(u1.x, u1.y)), h2u(__floats2half2_rn(u1.z, u1.w)));
        CP_COMMIT();
        CP_WAIT0();
    }
    __syncthreads();

    #pragma unroll 1
    for (int it = 0; it < HDIM / 32; it++) {
        int s = it & 1;
        bool more = (it + 1) < HDIM / 32;

        float4 g0, g1, u0, u1;
        if (more) {
            int k0 = (it + 1) * 32;
            cp16(asts + (s ^ 1) * ASTB, aptr + k0);
            cp16(asts + (s ^ 1) * ASTB + 16, aptr + k0 + 8);
            CP_COMMIT();
            g0 = *(const float4*)(gptr + (size_t)k0 * IDIM);
            g1 = *(const float4*)(gptr + (size_t)k0 * IDIM + 4);
            u0 = *(const float4*)(uptr + (size_t)k0 * IDIM);
            u1 = *(const float4*)(uptr + (size_t)k0 * IDIM + 4);
        }

        #pragma unroll
        for (int kc = 0; kc < 2; kc++) {
            unsigned af[2][4];
            #pragma unroll
            for (int mf = 0; mf < 2; mf++)
                ldsm_x4(af[mf][0], af[mf][1], af[mf][2], af[mf][3],
                        a_lds + s * ASTB + kc * 32 + mf * (16 * A_RW * 4));
            #pragma unroll
            for (int nf2 = 0; nf2 < 2; nf2++) {
                unsigned bg[4], bu[4];
                uint32_t bo = s * BSTB + kc * (16 * B_RW * 4) + nf2 * 32;
                ldsm_x4t(bg[0], bg[1], bg[2], bg[3], bg_lds + bo);
                ldsm_x4t(bu[0], bu[1], bu[2], bu[3], bu_lds + bo);
                int nf = nf2 * 2;
                mma_f16(accg[0][nf],     af[0], bg[0], bg[1]);
                mma_f16(accg[1][nf],     af[1], bg[0], bg[1]);
                mma_f16(accg[0][nf + 1], af[0], bg[2], bg[3]);
                mma_f16(accg[1][nf + 1], af[1], bg[2], bg[3]);
                mma_f16(accu[0][nf],     af[0], bu[0], bu[1]);
                mma_f16(accu[1][nf],     af[1], bu[0], bu[1]);
                mma_f16(accu[0][nf + 1], af[0], bu[2], bu[3]);
                mma_f16(accu[1][nf + 1], af[1], bu[2], bu[3]);
            }
        }

        if (more) {
            int nb = (s ^ 1) * BSTW;
            *(uint4*)&Bgh[nb + bsts] = make_uint4(
                h2u(__floats2half2_rn(g0.x, g0.y)), h2u(__floats2half2_rn(g0.z, g0.w)),
                h2u(__floats2half2_rn(g1.x, g1.y)), h2u(__floats2half2_rn(g1.z, g1.w)));
            *(uint4*)&Buh[nb + bsts] = make_uint4(
                h2u(__floats2half2_rn(u0.x, u0.y)), h2u(__floats2half2_rn(u0.z, u0.w)),
                h2u(__floats2half2_rn(u1.x, u1.y)), h2u(__floats2half2_rn(u1.z, u1.w)));
            CP_WAIT0();
        }
        __syncthreads();
    }

    int base = g_off[e] + m0;
    #pragma unroll
    for (int mf = 0; mf < 2; mf++) {
        int r0 = wm + mf * 16 + gid;
        int r1 = r0 + 8;
        #pragma unroll
        for (int nf = 0; nf < 4; nf++) {
            int col = n0 + wn + nf * 8 + 2 * p;
            if (m0 + r0 < cnt) {
                float g0 = accg[mf][nf][0], g1 = accg[mf][nf][1];
                float u0 = accu[mf][nf][0], u1 = accu[mf][nf][1];
                *(__half2*)(g_hidden + (size_t)(base + r0) * IDIM + col)
                    = __floats2half2_rn((g0 / (1.f + __expf(-g0))) * u0,
                                        (g1 / (1.f + __expf(-g1))) * u1);
            }
            if (m0 + r1 < cnt) {
                float g2 = accg[mf][nf][2], g3 = accg[mf][nf][3];
                float u2 = accu[mf][nf][2], u3 = accu[mf][nf][3];
                *(__half2*)(g_hidden + (size_t)(base + r1) * IDIM + col)
                    = __floats2half2_rn((g2 / (1.f + __expf(-g2))) * u2,
                                        (g3 / (1.f + __expf(-g3))) * u3);
            }
        }
    }
}

// ======== gemm2: fp16 mma.sync + ldmatrix(x4t), 128x128 block, 32x64 warp tile ========
// grid (HDIM/128=8, 16, NEXP), 256 threads, 8 warps = 4m x 2n; fp16 output
__global__ __launch_bounds__(256, 2) void moe_gemm2(const float* __restrict__ wd_all) {
    int e   = blockIdx.z;
    int cnt = g_cnt[e];
    int m0  = blockIdx.y * 128;
    if (m0 >= cnt) return;
    int n0  = blockIdx.x * 128;

    const float* wd = wd_all + (size_t)e * IDIM * HDIM;
    int base = g_off[e] + m0;

    __shared__ __align__(16) unsigned Ash[2 * ASTW];
    __shared__ __align__(16) unsigned Bsh[2 * B2STW];

    int tid = threadIdx.x;
    int lane = tid & 31, warp = tid >> 5;
    int wm = (warp >> 1) * 32, wn = (warp & 1) * 64;
    int gid = lane >> 2, p = lane & 3;

    uint32_t As_u = smem_u32(Ash);
    uint32_t Bs_u = smem_u32(Bsh);

    uint32_t a_lds = As_u + (((wm + (lane & 15)) * A_RW + (lane >> 4) * 4) << 2);
    uint32_t b_lds = Bs_u + ((((lane & 15) * B2_RW) + (wn >> 1) + ((lane >> 4) << 2)) << 2);

    int arow = tid >> 1, achunk = tid & 1;
    const __half* aptr = g_hidden + (size_t)(base + arow) * IDIM + achunk * 16;
    uint32_t asts = As_u + arow * (A_RW * 4) + achunk * 32;

    int bkr = tid >> 3, bnq = tid & 7;
    const float* bptr = wd + (size_t)bkr * HDIM + n0 + bnq * 16;
    int bsts = bkr * B2_RW + bnq * 8;

    float acc[2][8][4] = {};

    {
        cp16(asts, aptr);
        cp16(asts + 16, aptr + 8);
        float4 b0 = *(const float4*)bptr;
        float4 b1 = *(const float4*)(bptr + 4);
        float4 b2 = *(const float4*)(bptr + 8);
        float4 b3 = *(const float4*)(bptr + 12);
        *(uint4*)&Bsh[bsts] = make_uint4(
            h2u(__floats2half2_rn(b0.x, b0.y)), h2u(__floats2half2_rn(b0.z, b0.w)),
            h2u(__floats2half2_rn(b1.x, b1.y)), h2u(__floats2half2_rn(b1.z, b1.w)));
        *(uint4*)&Bsh[bsts + 4] = make_uint4(
            h2u(__floats2half2_rn(b2.x, b2.y)), h2u(__floats2half2_rn(b2.z, b2.w)),
            h2u(__floats2half2_rn(b3.x, b3.y)), h2u(__floats2half2_rn(b3.z, b3.w)));
        CP_COMMIT();
        CP_WAIT0();
    }
    __syncthreads();

    #pragma unroll 1
    for (int it = 0; it < IDIM / 32; it++) {
        int s = it & 1;
        bool more = (it + 1) < IDIM / 32;

        float4 b0v, b1v, b2v, b3v;
        if (more) {
            int k0 = (it + 1) * 32;
            cp16(asts + (s ^ 1) * ASTB, aptr + k0);
            cp16(asts + (s ^ 1) * ASTB + 16, aptr + k0 + 8);
            CP_COMMIT();
            b0v = *(const float4*)(bptr + (size_t)k0 * HDIM);
            b1v = *(const float4*)(bptr + (size_t)k0 * HDIM + 4);
            b2v = *(const float4*)(bptr + (size_t)k0 * HDIM + 8);
            b3v = *(const float4*)(bptr + (size_t)k0 * HDIM + 12);
        }

        #pragma unroll
        for (int kc = 0; kc < 2; kc++) {
            unsigned af[2][4];
            #pragma unroll
            for (int mf = 0; mf < 2; mf++)
                ldsm_x4(af[mf][0], af[mf][1], af[mf][2], af[mf][3],
                        a_lds + s * ASTB + kc * 32 + mf * (16 * A_RW * 4));
            #pragma unroll
            for (int nf2 = 0; nf2 < 4; nf2++) {
                unsigned bb[4];
                uint32_t bo = s * B2STB + kc * (16 * B2_RW * 4) + nf2 * 32;
                ldsm_x4t(bb[0], bb[1], bb[2], bb[3], b_lds + bo);
                int nf = nf2 * 2;
                mma_f16(acc[0][nf],     af[0], bb[0], bb[1]);
                mma_f16(acc[1][nf],     af[1], bb[0], bb[1]);
                mma_f16(acc[0][nf + 1], af[0], bb[2], bb[3]);
                mma_f16(acc[1][nf + 1], af[1], bb[2], bb[3]);
            }
        }

        if (more) {
            int nb = (s ^ 1) * B2STW;
            *(uint4*)&Bsh[nb + bsts] = make_uint4(
                h2u(__floats2half2_rn(b0v.x, b0v.y)), h2u(__floats2half2_rn(b0v.z, b0v.w)),
                h2u(__floats2half2_rn(b1v.x, b1v.y)), h2u(__floats2half2_rn(b1v.z, b1v.w)));
            *(uint4*)&Bsh[nb + bsts + 4] = make_uint4(
                h2u(__floats2half2_rn(b2v.x, b2v.y)), h2u(__floats2half2_rn(b2v.z, b2v.w)),
                h2u(__floats2half2_rn(b3v.x, b3v.y)), h2u(__floats2half2_rn(b3v.z, b3v.w)));
            CP_WAIT0();
        }
        __syncthreads();
    }

    #pragma unroll
    for (int mf = 0; mf < 2; mf++) {
        int r0 = wm + mf * 16 + gid;
        int r1 = r0 + 8;
        #pragma unroll
        for (int nf = 0; nf < 8; nf++) {
            int col = n0 + wn + nf * 8 + 2 * p;
            if (m0 + r0 < cnt)
                *(__half2*)(g_downh + (size_t)(base + r0) * HDIM + col)
                    = __floats2half2_rn(acc[mf][nf][0], acc[mf][nf][1]);
            if (m0 + r1 < cnt)
                *(__half2*)(g_downh + (size_t)(base + r1) * HDIM + col)
                    = __floats2half2_rn(acc[mf][nf][2], acc[mf][nf][3]);
        }
    }
}

// ---------------- combine (fp16 reads, fp32 accumulate; + counter reset) ----------------
__global__ void combine_kernel(float* __restrict__ out) {
    int t = blockIdx.x;
    int h = threadIdx.x * 4;
    float acc0 = 0.f, acc1 = 0.f, acc2 = 0.f, acc3 = 0.f;
    #pragma unroll
    for (int k = 0; k < TOPK; k++) {
        int   e = g_sel_e[t * TOPK + k];
        int   a = g_off[e] + g_sel_slot[t * TOPK + k];
        float w = g_sel_w[t * TOPK + k];
        const __half2* src = (const __half2*)(g_downh + (size_t)a * HDIM + h);
        float2 v0 = __half22float2(src[0]);
        float2 v1 = __half22float2(src[1]);
        acc0 += w * v0.x; acc1 += w * v0.y;
        acc2 += w * v1.x; acc3 += w * v1.y;
    }
    *(float4*)(out + (size_t)t * HDIM + h) = make_float4(acc0, acc1, acc2, acc3);

    if (blockIdx.x == 0 && threadIdx.x < NEXP) g_cnt[threadIdx.x] = 0;
}

// ---------------- launch ----------------
extern "C" void kernel_launch(void* const* d_in, const int* in_sizes, int n_in,
                              void* d_out, int out_size) {
    const float* x   = (const float*)d_in[0];
    const float* wgt = (const float*)d_in[1];
    const float* wgp = (const float*)d_in[2];
    const float* wup = (const float*)d_in[3];
    const float* wdp = (const float*)d_in[4];
    float* out = (float*)d_out;

    int write_logits = (out_size >= T_TOK * HDIM + T_TOK * NEXP) ? 1 : 0;
    float* logits_out = out + (size_t)T_TOK * HDIM;

    router_kernel<<<T_TOK / 16, 256>>>(x, wgt, logits_out, write_logits);
    moe_gemm1<<<dim3(IDIM / 64, T_TOK / 128, NEXP), 256>>>(wgp, wup);
    moe_gemm2<<<dim3(HDIM / 128, T_TOK / 128, NEXP), 256>>>(wdp);
    combine_kernel<<<T_TOK, HDIM / 4>>>(out);
}